// round 2
// baseline (speedup 1.0000x reference)
#include <cuda_runtime.h>
#include <cuda_bf16.h>

#define MAX_NODES 100000
#define DIM 64
#define LN_EPS 1e-5f

// Scratch (no cudaMalloc allowed)
__device__ float g_agg[MAX_NODES * DIM];
__device__ float g_deg[MAX_NODES];
__device__ unsigned g_is64;

// ---------------------------------------------------------------------------
// Detect whether edge_index is int64 or int32 (JAX x64-off silently downcasts).
// int64 little-endian layout has all odd 32-bit words == 0 (values < 100000).
// int32 layout: odd words are random indices — P(512 samples all zero) ~ 0.
// ---------------------------------------------------------------------------
__global__ void detect_dtype_kernel(const unsigned* __restrict__ ei_raw) {
    __shared__ unsigned s_any;
    if (threadIdx.x == 0) s_any = 0u;
    __syncthreads();
    unsigned v = 0;
    // scan odd words among the first 2048 u32 words (buffer >= 9.6MB, safe)
    for (int i = 2 * threadIdx.x + 1; i < 2048; i += 2 * blockDim.x)
        v |= ei_raw[i];
    if (v) atomicOr(&s_any, 1u);
    __syncthreads();
    if (threadIdx.x == 0) g_is64 = (s_any == 0u) ? 1u : 0u;
}

// ---------------------------------------------------------------------------
// Zero the accumulation buffers.
// ---------------------------------------------------------------------------
__global__ void zero_kernel(int n_nodes) {
    int i = blockIdx.x * blockDim.x + threadIdx.x;
    int total = n_nodes * DIM;
    if (i < total) g_agg[i] = 0.0f;
    if (i < n_nodes) g_deg[i] = 0.0f;
}

// ---------------------------------------------------------------------------
// Scatter-add: 8 threads per edge, each does 2x float4 gather + red.v4.f32.
// x[j] rows and agg both fit in L2 -> this is an L2/atomic-bound kernel.
// ---------------------------------------------------------------------------
__global__ void scatter_kernel(const float* __restrict__ x,
                               const void* __restrict__ ei,
                               int n_edges) {
    long long idx = (long long)blockIdx.x * blockDim.x + threadIdx.x;
    long long e = idx >> 3;
    int lane = (int)(idx & 7);
    if (e >= n_edges) return;

    long long dst, src;
    if (g_is64) {
        const long long* e64 = (const long long*)ei;
        dst = e64[e];
        src = e64[n_edges + e];
    } else {
        const int* e32 = (const int*)ei;
        dst = e32[e];
        src = e32[n_edges + e];
    }

    const float4* xs = (const float4*)(x + src * DIM);
    float* ag = g_agg + dst * DIM;

#pragma unroll
    for (int q = 0; q < 2; q++) {
        int c = lane * 2 + q;          // float4 index 0..15 within the row
        float4 v = xs[c];
        asm volatile(
            "red.global.add.v4.f32 [%0], {%1,%2,%3,%4};"
            :: "l"(ag + c * 4), "f"(v.x), "f"(v.y), "f"(v.z), "f"(v.w)
            : "memory");
    }
    if (lane == 0) atomicAdd(&g_deg[dst], 1.0f);
}

// ---------------------------------------------------------------------------
// Per-node: mean, concat-linear (W^T in shared, conflict-free), ReLU, LN.
// 256 threads = 4 nodes/block, 64 threads (one output dim each) per node.
// ---------------------------------------------------------------------------
__global__ void compute_kernel(const float* __restrict__ x,
                               const float* __restrict__ W,
                               const float* __restrict__ b,
                               const float* __restrict__ gamma,
                               const float* __restrict__ beta,
                               float* __restrict__ out,
                               int n_nodes) {
    __shared__ float sW[128 * 64];   // sW[k*64+o] = W[o*128+k]  (32 KB)
    __shared__ float sIn[4][128];
    __shared__ float sH[4][64];

    int tid = threadIdx.x;
    // Load W transposed: consecutive threads write consecutive sW entries? No —
    // we index by source i; writes are scattered but one-time (25 blocks reuse).
    for (int i = tid; i < 64 * 128; i += 256) {
        int o = i >> 7;
        int k = i & 127;
        sW[k * 64 + o] = W[i];
    }

    int g = tid >> 6;        // node group within block (0..3)
    int o = tid & 63;        // output dim
    int node = blockIdx.x * 4 + g;

    if (node < n_nodes) {
        float d = fmaxf(g_deg[node], 1.0f);
        sIn[g][o]      = x[(long long)node * DIM + o];
        sIn[g][64 + o] = g_agg[(long long)node * DIM + o] * (1.0f / d);
    }
    __syncthreads();

    if (node < n_nodes) {
        float acc = b[o];
#pragma unroll 8
        for (int k = 0; k < 128; k++)
            acc = fmaf(sIn[g][k], sW[k * 64 + o], acc);  // sIn broadcast, sW conflict-free
        acc = fmaxf(acc, 0.0f);
        sH[g][o] = acc;
    }
    __syncthreads();

    if (node < n_nodes) {
        float s = 0.0f, s2 = 0.0f;
#pragma unroll
        for (int k = 0; k < 64; k++) {
            float v = sH[g][k];            // broadcast within warp
            s += v;
            s2 = fmaf(v, v, s2);
        }
        float mu  = s * (1.0f / 64.0f);
        float var = s2 * (1.0f / 64.0f) - mu * mu;
        float h   = sH[g][o];
        out[(long long)node * DIM + o] =
            (h - mu) * rsqrtf(var + LN_EPS) * gamma[o] + beta[o];
    }
}

// ---------------------------------------------------------------------------
extern "C" void kernel_launch(void* const* d_in, const int* in_sizes, int n_in,
                              void* d_out, int out_size) {
    const float* x     = (const float*)d_in[0];   // [N, 64]
    const float* W     = (const float*)d_in[1];   // [64, 128]
    const float* b     = (const float*)d_in[2];   // [64]
    const float* gamma = (const float*)d_in[3];   // [64]
    const float* beta  = (const float*)d_in[4];   // [64]
    const void*  ei    = d_in[5];                 // [2, E] int32 or int64

    int n_nodes = in_sizes[0] / DIM;
    int n_edges = in_sizes[5] / 2;
    float* out = (float*)d_out;

    detect_dtype_kernel<<<1, 256>>>((const unsigned*)ei);

    int zero_total = n_nodes * DIM;
    zero_kernel<<<(zero_total + 255) / 256, 256>>>(n_nodes);

    long long sc_threads = (long long)n_edges * 8;
    int sc_blocks = (int)((sc_threads + 255) / 256);
    scatter_kernel<<<sc_blocks, 256>>>(x, ei, n_edges);

    compute_kernel<<<(n_nodes + 3) / 4, 256>>>(x, W, b, gamma, beta, out, n_nodes);
}

// round 3
// speedup vs baseline: 4.9505x; 4.9505x over previous
#include <cuda_runtime.h>
#include <cuda_bf16.h>

#define MAX_NODES 100000
#define DIM 64
#define LN_EPS 1e-5f

#define NPB 128            // nodes per block (compute kernel)
#define SIN_STRIDE 132     // padded row stride (floats) -> bank stride 4 for node-stride-1 readers

// Scratch (no cudaMalloc allowed)
__device__ float g_agg[MAX_NODES * DIM];
__device__ float g_deg[MAX_NODES];
__device__ unsigned g_is64;

// ---------------------------------------------------------------------------
// Detect int64 vs int32 edge_index (JAX x64-off silently downcasts).
// ---------------------------------------------------------------------------
__global__ void detect_dtype_kernel(const unsigned* __restrict__ ei_raw) {
    __shared__ unsigned s_any;
    if (threadIdx.x == 0) s_any = 0u;
    __syncthreads();
    unsigned v = 0;
    for (int i = 2 * threadIdx.x + 1; i < 2048; i += 2 * blockDim.x)
        v |= ei_raw[i];
    if (v) atomicOr(&s_any, 1u);
    __syncthreads();
    if (threadIdx.x == 0) g_is64 = (s_any == 0u) ? 1u : 0u;
}

// ---------------------------------------------------------------------------
__global__ void zero_kernel(int n_nodes) {
    int i = blockIdx.x * blockDim.x + threadIdx.x;
    int total = n_nodes * DIM;
    if (i < total) g_agg[i] = 0.0f;
    if (i < n_nodes) g_deg[i] = 0.0f;
}

// ---------------------------------------------------------------------------
// Scatter-add: 8 threads/edge, 2x red.global.add.v4.f32 each.
// ---------------------------------------------------------------------------
__global__ void scatter_kernel(const float* __restrict__ x,
                               const void* __restrict__ ei,
                               int n_edges) {
    long long idx = (long long)blockIdx.x * blockDim.x + threadIdx.x;
    long long e = idx >> 3;
    int lane = (int)(idx & 7);
    if (e >= n_edges) return;

    long long dst, src;
    if (g_is64) {
        const long long* e64 = (const long long*)ei;
        dst = e64[e];
        src = e64[n_edges + e];
    } else {
        const int* e32 = (const int*)ei;
        dst = e32[e];
        src = e32[n_edges + e];
    }

    const float4* xs = (const float4*)(x + src * DIM);
    float* ag = g_agg + dst * DIM;

#pragma unroll
    for (int q = 0; q < 2; q++) {
        int c = lane * 2 + q;
        float4 v = xs[c];
        asm volatile(
            "red.global.add.v4.f32 [%0], {%1,%2,%3,%4};"
            :: "l"(ag + c * 4), "f"(v.x), "f"(v.y), "f"(v.z), "f"(v.w)
            : "memory");
    }
    if (lane == 0) atomicAdd(&g_deg[dst], 1.0f);
}

// ---------------------------------------------------------------------------
// Fused GEMM (M=NPB, N=64, K=128) + ReLU + LayerNorm.
// 256 threads, 8 warps. Each warp: 16 nodes. Lane tile: 4 nodes x 8 outputs.
//   lane mapping: n_group = lane & 3, o_group = lane >> 2
//   node(n)      = blk*NPB + wid*16 + n_group + 4*n      (n = 0..3)
//   outputs      = o_group*8 + 0..7
// LN via shfl_xor over the 8 o_groups (masks 4, 8, 16). No smem in LN phase.
// Dynamic smem: sW[128*64] + sIn[NPB*SIN_STRIDE].
// ---------------------------------------------------------------------------
__global__ void compute_kernel(const float* __restrict__ x,
                               const float* __restrict__ W,
                               const float* __restrict__ b,
                               const float* __restrict__ gamma,
                               const float* __restrict__ beta,
                               float* __restrict__ out,
                               int n_nodes) {
    extern __shared__ float smem[];
    float* sW  = smem;                 // [128][64], sW[k*64+o] = W[o*128+k]
    float* sIn = smem + 128 * 64;      // [NPB][SIN_STRIDE]

    int tid = threadIdx.x;
    int base = blockIdx.x * NPB;

    // --- load + transpose W (once per block, amortized over 128 nodes) ---
    for (int i = tid; i < 64 * 128; i += 256) {
        int o = i >> 7;
        int k = i & 127;
        sW[k * 64 + o] = W[i];
    }

    // --- fill sIn: [x_row | agg_row/deg], float4 granularity ---
    // 128 nodes * 32 float4 (16 x-part + 16 agg-part) = 4096 float4 ops, 16/thread
    for (int i = tid; i < NPB * 32; i += 256) {
        int n = i >> 5;            // local node
        int c = i & 31;            // float4 slot within 128-float row
        int node = base + n;
        float4 v = make_float4(0.f, 0.f, 0.f, 0.f);
        if (node < n_nodes) {
            if (c < 16) {
                v = ((const float4*)(x + (long long)node * DIM))[c];
            } else {
                v = ((const float4*)(g_agg + (long long)node * DIM))[c - 16];
                float inv = 1.0f / fmaxf(g_deg[node], 1.0f);
                v.x *= inv; v.y *= inv; v.z *= inv; v.w *= inv;
            }
        }
        *((float4*)(sIn + n * SIN_STRIDE + c * 4)) = v;
    }
    __syncthreads();

    // --- register-tiled GEMM ---
    int lane = tid & 31;
    int wid  = tid >> 5;
    int n_group = lane & 3;
    int o_group = lane >> 2;          // 0..7

    const float* in0 = sIn + (wid * 16 + n_group) * SIN_STRIDE;   // node stride 4*SIN_STRIDE
    const float4* sWv = (const float4*)sW;                        // 16 float4 per k-row

    float acc[4][8];
#pragma unroll
    for (int n = 0; n < 4; n++)
#pragma unroll
        for (int j = 0; j < 8; j++) acc[n][j] = 0.0f;

#pragma unroll 4
    for (int k = 0; k < 128; k++) {
        float4 w0 = sWv[k * 16 + o_group * 2];
        float4 w1 = sWv[k * 16 + o_group * 2 + 1];
        float a0 = in0[0 * 4 * SIN_STRIDE + k];
        float a1 = in0[1 * 4 * SIN_STRIDE + k];
        float a2 = in0[2 * 4 * SIN_STRIDE + k];
        float a3 = in0[3 * 4 * SIN_STRIDE + k];
        float av[4] = {a0, a1, a2, a3};
#pragma unroll
        for (int n = 0; n < 4; n++) {
            acc[n][0] = fmaf(av[n], w0.x, acc[n][0]);
            acc[n][1] = fmaf(av[n], w0.y, acc[n][1]);
            acc[n][2] = fmaf(av[n], w0.z, acc[n][2]);
            acc[n][3] = fmaf(av[n], w0.w, acc[n][3]);
            acc[n][4] = fmaf(av[n], w1.x, acc[n][4]);
            acc[n][5] = fmaf(av[n], w1.y, acc[n][5]);
            acc[n][6] = fmaf(av[n], w1.z, acc[n][6]);
            acc[n][7] = fmaf(av[n], w1.w, acc[n][7]);
        }
    }

    // --- bias + ReLU + LayerNorm (in registers, shfl across 8 o_groups) ---
    float bb[8], gg[8], be[8];
#pragma unroll
    for (int j = 0; j < 8; j++) {
        int o = o_group * 8 + j;
        bb[j] = b[o];
        gg[j] = gamma[o];
        be[j] = beta[o];
    }

#pragma unroll
    for (int n = 0; n < 4; n++) {
        int node = base + wid * 16 + n_group + 4 * n;
        float s = 0.0f, s2 = 0.0f;
#pragma unroll
        for (int j = 0; j < 8; j++) {
            float h = fmaxf(acc[n][j] + bb[j], 0.0f);
            acc[n][j] = h;
            s += h;
            s2 = fmaf(h, h, s2);
        }
        // reduce over the 8 lanes (same n_group) holding this node's outputs
#pragma unroll
        for (int m = 4; m <= 16; m <<= 1) {
            s  += __shfl_xor_sync(0xFFFFFFFFu, s,  m);
            s2 += __shfl_xor_sync(0xFFFFFFFFu, s2, m);
        }
        float mu  = s * (1.0f / 64.0f);
        float var = s2 * (1.0f / 64.0f) - mu * mu;
        float rstd = rsqrtf(var + LN_EPS);

        if (node < n_nodes) {
            float4 v0, v1;
            v0.x = (acc[n][0] - mu) * rstd * gg[0] + be[0];
            v0.y = (acc[n][1] - mu) * rstd * gg[1] + be[1];
            v0.z = (acc[n][2] - mu) * rstd * gg[2] + be[2];
            v0.w = (acc[n][3] - mu) * rstd * gg[3] + be[3];
            v1.x = (acc[n][4] - mu) * rstd * gg[4] + be[4];
            v1.y = (acc[n][5] - mu) * rstd * gg[5] + be[5];
            v1.z = (acc[n][6] - mu) * rstd * gg[6] + be[6];
            v1.w = (acc[n][7] - mu) * rstd * gg[7] + be[7];
            float4* op = (float4*)(out + (long long)node * DIM + o_group * 8);
            op[0] = v0;
            op[1] = v1;
        }
    }
}

// ---------------------------------------------------------------------------
extern "C" void kernel_launch(void* const* d_in, const int* in_sizes, int n_in,
                              void* d_out, int out_size) {
    const float* x     = (const float*)d_in[0];   // [N, 64]
    const float* W     = (const float*)d_in[1];   // [64, 128]
    const float* b     = (const float*)d_in[2];   // [64]
    const float* gamma = (const float*)d_in[3];   // [64]
    const float* beta  = (const float*)d_in[4];   // [64]
    const void*  ei    = d_in[5];                 // [2, E] int32 or int64

    int n_nodes = in_sizes[0] / DIM;
    int n_edges = in_sizes[5] / 2;
    float* out = (float*)d_out;

    detect_dtype_kernel<<<1, 256>>>((const unsigned*)ei);

    int zero_total = n_nodes * DIM;
    zero_kernel<<<(zero_total + 255) / 256, 256>>>(n_nodes);

    long long sc_threads = (long long)n_edges * 8;
    int sc_blocks = (int)((sc_threads + 255) / 256);
    scatter_kernel<<<sc_blocks, 256>>>(x, ei, n_edges);

    int smem_bytes = (128 * 64 + NPB * SIN_STRIDE) * sizeof(float);  // ~100 KB
    cudaFuncSetAttribute(compute_kernel,
                         cudaFuncAttributeMaxDynamicSharedMemorySize, smem_bytes);
    compute_kernel<<<(n_nodes + NPB - 1) / NPB, 256, smem_bytes>>>(
        x, W, b, gamma, beta, out, n_nodes);
}